// round 8
// baseline (speedup 1.0000x reference)
#include <cuda_runtime.h>
#include <cstddef>

#define N_STEPS 4096
#define NU 8
#define R 256
#define NX 64
#define NY 8
#define L 16
#define C_CHUNKS (N_STEPS / L)   // 256
#define QTOT (NU * L)            // 128

typedef unsigned long long ull;

// Scratch (device globals: no allocation allowed in kernel_launch)
__device__ float g_KcatT[QTOT * NX];   // [q][i], q=(t*NU+j) holds (A^{L-1-t}B)^T
__device__ float g_AL[NX * NX];        // A^L row-major
__device__ float g_buf[(size_t)C_CHUNKS * NX * R];  // Pfin, overwritten by Xstart

// ---------------- packed f32x2 helpers ----------------
__device__ __forceinline__ ull pack2(float lo, float hi) {
    ull v; asm("mov.b64 %0,{%1,%2};" : "=l"(v) : "f"(lo), "f"(hi)); return v;
}
__device__ __forceinline__ void unpack2(ull v, float& lo, float& hi) {
    asm("mov.b64 {%0,%1},%2;" : "=f"(lo), "=f"(hi) : "l"(v));
}
// IN-PLACE packed fma: no output-register copy
__device__ __forceinline__ void fma2ip(ull& d, ull a, ull b) {
    asm("fma.rn.f32x2 %0,%1,%2,%0;" : "+l"(d) : "l"(a), "l"(b));
}

// ---------------------------------------------------------------------------
// Kernel 0: K[s]=A^s B (s=0..15) by doubling (4 rounds) and A^16, all in smem.
// ---------------------------------------------------------------------------
extern __shared__ float psm[];
__global__ void k_precompute(const float* __restrict__ A, const float* __restrict__ B) {
    float* sP = psm;            // 4096
    float* sQ = psm + 4096;     // 4096
    float* sW = psm + 8192;     // [i][col], stride 128
    const int t = threadIdx.x;  // 512

    for (int idx = t; idx < NX * NX; idx += 512) sP[idx] = A[idx];
    for (int idx = t; idx < NX * NU; idx += 512) {
        int i = idx / NU, j = idx % NU;
        sW[i * QTOT + j] = B[idx];
    }
    __syncthreads();

    float* p = sP;
    float* q = sQ;
    int w = NU;  // 8 -> 16 -> 32 -> 64 -> 128
    for (int m = 0; m < 4; m++) {
        for (int idx = t; idx < NX * w; idx += 512) {
            int i = idx / w, jc = idx % w;
            float a0 = 0.f, a1 = 0.f, a2 = 0.f, a3 = 0.f;
            #pragma unroll 4
            for (int k = 0; k < NX; k += 4) {
                a0 += p[i * NX + k + 0] * sW[(k + 0) * QTOT + jc];
                a1 += p[i * NX + k + 1] * sW[(k + 1) * QTOT + jc];
                a2 += p[i * NX + k + 2] * sW[(k + 2) * QTOT + jc];
                a3 += p[i * NX + k + 3] * sW[(k + 3) * QTOT + jc];
            }
            sW[i * QTOT + w + jc] = (a0 + a1) + (a2 + a3);
        }
        __syncthreads();
        for (int idx = t; idx < NX * NX; idx += 512) {
            int i = idx >> 6, j = idx & 63;
            float a0 = 0.f, a1 = 0.f, a2 = 0.f, a3 = 0.f;
            #pragma unroll 4
            for (int k = 0; k < NX; k += 4) {
                a0 += p[i * NX + k + 0] * p[(k + 0) * NX + j];
                a1 += p[i * NX + k + 1] * p[(k + 1) * NX + j];
                a2 += p[i * NX + k + 2] * p[(k + 2) * NX + j];
                a3 += p[i * NX + k + 3] * p[(k + 3) * NX + j];
            }
            q[idx] = (a0 + a1) + (a2 + a3);
        }
        __syncthreads();
        float* tmp = p; p = q; q = tmp;
        w *= 2;
    }
    for (int idx = t; idx < NX * NX; idx += 512) g_AL[idx] = p[idx];
    for (int idx = t; idx < NX * QTOT; idx += 512) {
        int i = idx >> 7, col = idx & 127;
        int s = col >> 3, j = col & 7;
        g_KcatT[(((L - 1 - s) * NU + j) * NX) + i] = sW[i * QTOT + col];
    }
}

// ---------------------------------------------------------------------------
// Kernel 1: Pfin[c] = Kcat(64x128) @ Uc(128x256) -> g_buf. Grid (256,4), 256 thr.
// ---------------------------------------------------------------------------
__global__ void k_phase1(const float* __restrict__ u) {
    __shared__ __align__(16) float sU[64 * 64];
    __shared__ __align__(16) float sKT[64 * 64];
    const int c = blockIdx.x;
    const int r0 = blockIdx.y * 64;
    const int t = threadIdx.x;
    const int r = t & 63;
    const int ig = t >> 6;

    ull acc2[8];
    #pragma unroll
    for (int m = 0; m < 8; m++) acc2[m] = 0ull;

    const float* Uc = u + (size_t)c * L * NU * R;

    for (int qb = 0; qb < QTOT / 64; qb++) {
        __syncthreads();
        #pragma unroll
        for (int m = 0; m < 16; m++) {
            int qq = m * 4 + ig;
            sU[qq * 64 + r] = Uc[(size_t)(qb * 64 + qq) * R + r0 + r];
        }
        for (int idx = t; idx < 4096; idx += 256)
            sKT[idx] = g_KcatT[qb * 64 * 64 + idx];
        __syncthreads();

        #pragma unroll 8
        for (int qq = 0; qq < 64; qq++) {
            float uval = sU[qq * 64 + r];
            ull uv = pack2(uval, uval);
            const ulonglong2* k2p = (const ulonglong2*)(sKT + qq * 64 + ig * 16);
            #pragma unroll
            for (int m2 = 0; m2 < 4; m2++) {
                ulonglong2 kk = k2p[m2];
                fma2ip(acc2[2 * m2 + 0], kk.x, uv);
                fma2ip(acc2[2 * m2 + 1], kk.y, uv);
            }
        }
    }
    #pragma unroll
    for (int m = 0; m < 8; m++) {
        float lo, hi; unpack2(acc2[m], lo, hi);
        int i = ig * 16 + 2 * m;
        g_buf[((size_t)c * NX + i) * R + r0 + r]     = lo;
        g_buf[((size_t)c * NX + i + 1) * R + r0 + r] = hi;
    }
}

// ---------------------------------------------------------------------------
// Kernel 2: boundary scan, 256 iters. A^16-row in packed regs; x via LDS.64.
// ---------------------------------------------------------------------------
__global__ void k_phase2(const float* __restrict__ x0) {
    __shared__ __align__(16) float sxf[2][2][NX];  // [buf][r][i]
    const int t = threadIdx.x;  // 128
    const int r = t & 1;
    const int i = t >> 1;
    const int rg = blockIdx.x * 2 + r;

    ull a2[32];
    const ull* arow = (const ull*)(g_AL + i * NX);
    #pragma unroll
    for (int j2 = 0; j2 < 32; j2++) a2[j2] = arow[j2];

    float xi = x0[i * R + rg];
    sxf[0][r][i] = xi;
    __syncthreads();

    int p = 0;
    float pf = g_buf[(size_t)i * R + rg];
    for (int c = 0; c < C_CHUNKS; c++) {
        float pf_next = (c + 1 < C_CHUNKS)
            ? g_buf[((size_t)(c + 1) * NX + i) * R + rg] : 0.f;
        g_buf[((size_t)c * NX + i) * R + rg] = xi;   // Xstart[c]

        const ull* xsrc = (const ull*)&sxf[p][r][0];
        ull A0 = 0ull, A1 = 0ull, A2 = 0ull, A3 = 0ull;
        #pragma unroll
        for (int j2 = 0; j2 < 32; j2 += 4) {
            fma2ip(A0, a2[j2 + 0], xsrc[j2 + 0]);
            fma2ip(A1, a2[j2 + 1], xsrc[j2 + 1]);
            fma2ip(A2, a2[j2 + 2], xsrc[j2 + 2]);
            fma2ip(A3, a2[j2 + 3], xsrc[j2 + 3]);
        }
        float s0, s1, s2, s3, s4, s5, s6, s7;
        unpack2(A0, s0, s1); unpack2(A1, s2, s3);
        unpack2(A2, s4, s5); unpack2(A3, s6, s7);
        xi = (((s0 + s1) + (s2 + s3)) + ((s4 + s5) + (s6 + s7))) + pf;

        sxf[p ^ 1][r][i] = xi;
        pf = pf_next;
        __syncthreads();
        p ^= 1;
    }
}

// ---------------------------------------------------------------------------
// Kernel 3 (v6): ONE column per thread, packed f32x2 in-place, x_k in 16KB
// smem scratch. 64 threads (2 warps), grid (C_CHUNKS, 4) = 1024 CTAs =
// 2048 warps (2x R7). smem 36.3KB -> 6 CTAs/SM = 12 warps/SM.
// ---------------------------------------------------------------------------
extern __shared__ __align__(16) char dsmem[];

__global__ void __launch_bounds__(64) k_phase3(
    const float* __restrict__ u, const float* __restrict__ A,
    const float* __restrict__ B, const float* __restrict__ Cy,
    const float* __restrict__ D,
    float* __restrict__ outY, float* __restrict__ outX)
{
    ull*   xs  = (ull*)dsmem;                          // [32][64] packed x pairs
    ull*   sA2 = (ull*)(dsmem + 16384);                // [j][i2] 64x32
    ull*   sB2 = (ull*)(dsmem + 16384 + 16384);        // [j][i2] 8x32
    ull*   sC2 = (ull*)(dsmem + 16384 + 16384 + 2048); // [o][j2] 8x32
    float* sD  = (float*)(dsmem + 16384 + 16384 + 4096);

    const int tid = threadIdx.x;                       // 64
    const int c = blockIdx.x;
    const int r = blockIdx.y * 64 + tid;               // this thread's column

    for (int idx = tid; idx < 64 * 32; idx += 64) {
        int j = idx >> 5, i2 = idx & 31;
        sA2[idx] = pack2(A[(2 * i2) * NX + j], A[(2 * i2 + 1) * NX + j]);
    }
    for (int idx = tid; idx < NU * 32; idx += 64) {
        int j = idx >> 5, i2 = idx & 31;
        sB2[idx] = pack2(B[(2 * i2) * NU + j], B[(2 * i2 + 1) * NU + j]);
    }
    for (int idx = tid; idx < NY * 32; idx += 64) {
        int o = idx >> 5, j2 = idx & 31;
        sC2[idx] = pack2(Cy[o * NX + 2 * j2], Cy[o * NX + 2 * j2 + 1]);
    }
    if (tid < NY * NU) sD[tid] = D[tid];

    // acc <- starting state of this chunk (g_buf = Xstart)
    ull acc2[32];
    {
        const float* xsa = g_buf + (size_t)c * NX * R + r;
        #pragma unroll
        for (int k = 0; k < 32; k++)
            acc2[k] = pack2(xsa[(2 * k) * R], xsa[(2 * k + 1) * R]);
    }
    __syncthreads();

    const float* up = u    + (size_t)c * L * NU * R + r;
    float*       yp = outY + (size_t)c * L * NY * R + r;
    float*       xp = outX + (size_t)c * L * NX * R + r;

    #pragma unroll 1
    for (int step = 0; step < L; step++) {
        // ---- inputs ----
        float uu[NU];
        #pragma unroll
        for (int j = 0; j < NU; j++) uu[j] = up[j * R];

        // ---- Y[k] = C x_k + D u_k (x_k = acc2) ----
        #pragma unroll 2
        for (int o = 0; o < NY; o++) {
            ull ya = 0ull;
            const ulonglong2* c2 = (const ulonglong2*)(sC2 + o * 32);
            #pragma unroll
            for (int k2 = 0; k2 < 16; k2++) {
                ulonglong2 cc = c2[k2];
                fma2ip(ya, cc.x, acc2[2 * k2 + 0]);
                fma2ip(ya, cc.y, acc2[2 * k2 + 1]);
            }
            float lo, hi; unpack2(ya, lo, hi);
            float ds = 0.f;
            #pragma unroll
            for (int j = 0; j < NU; j++) ds += sD[o * NU + j] * uu[j];
            yp[o * R] = (lo + hi) + ds;
        }

        // ---- store X[k] to gmem + packed smem scratch ----
        #pragma unroll
        for (int k = 0; k < 32; k++) {
            float lo, hi; unpack2(acc2[k], lo, hi);
            xp[(2 * k) * R]     = lo;
            xp[(2 * k + 1) * R] = hi;
            xs[k * 64 + tid]    = acc2[k];
        }

        // ---- acc = B u ----
        #pragma unroll
        for (int k = 0; k < 32; k++) acc2[k] = 0ull;
        #pragma unroll 2
        for (int j = 0; j < NU; j++) {
            ull uvj = pack2(uu[j], uu[j]);
            const ulonglong2* bj = (const ulonglong2*)(sB2 + j * 32);
            #pragma unroll
            for (int k2 = 0; k2 < 16; k2++) {
                ulonglong2 bb = bj[k2];
                fma2ip(acc2[2 * k2 + 0], bb.x, uvj);
                fma2ip(acc2[2 * k2 + 1], bb.y, uvj);
            }
        }

        // ---- acc += A x_k ----
        #pragma unroll 2
        for (int j2 = 0; j2 < 32; j2++) {
            ull pa = xs[j2 * 64 + tid];
            float xa0, xa1; unpack2(pa, xa0, xa1);
            ull sa0 = pack2(xa0, xa0), sa1 = pack2(xa1, xa1);
            const ulonglong2* A0 = (const ulonglong2*)(sA2 + (2 * j2) * 32);
            const ulonglong2* A1 = (const ulonglong2*)(sA2 + (2 * j2 + 1) * 32);
            #pragma unroll
            for (int k2 = 0; k2 < 16; k2++) {
                ulonglong2 aa = A0[k2];
                fma2ip(acc2[2 * k2 + 0], aa.x, sa0);
                fma2ip(acc2[2 * k2 + 1], aa.y, sa0);
                ulonglong2 ab = A1[k2];
                fma2ip(acc2[2 * k2 + 0], ab.x, sa1);
                fma2ip(acc2[2 * k2 + 1], ab.y, sa1);
            }
        }

        up += NU * R;
        yp += NY * R;
        xp += NX * R;
    }
}

#define SMEM_P3 (16384 + 16384 + 2048 + 2048 + 256)
#define SMEM_P0 ((4096 + 4096 + 8192) * 4)

// ---------------------------------------------------------------------------
extern "C" void kernel_launch(void* const* d_in, const int* in_sizes, int n_in,
                              void* d_out, int out_size) {
    const float* u  = (const float*)d_in[0];
    const float* x0 = (const float*)d_in[1];
    const float* A  = (const float*)d_in[2];
    const float* B  = (const float*)d_in[3];
    const float* Cy = (const float*)d_in[4];
    const float* D  = (const float*)d_in[5];
    float* outY = (float*)d_out;
    float* outX = (float*)d_out + (size_t)N_STEPS * NY * R;

    cudaFuncSetAttribute(k_phase3, cudaFuncAttributeMaxDynamicSharedMemorySize, SMEM_P3);
    cudaFuncSetAttribute(k_precompute, cudaFuncAttributeMaxDynamicSharedMemorySize, SMEM_P0);

    k_precompute<<<1, 512, SMEM_P0>>>(A, B);
    k_phase1<<<dim3(C_CHUNKS, R / 64), 256>>>(u);
    k_phase2<<<R / 2, 128>>>(x0);
    k_phase3<<<dim3(C_CHUNKS, 4), 64, SMEM_P3>>>(u, A, B, Cy, D, outY, outX);
}

// round 9
// speedup vs baseline: 1.3686x; 1.3686x over previous
#include <cuda_runtime.h>
#include <cstddef>

#define N_STEPS 4096
#define NU 8
#define R 256
#define NX 64
#define NY 8
#define L 16
#define C_CHUNKS (N_STEPS / L)   // 256
#define QTOT (NU * L)            // 128

typedef unsigned long long ull;

// Scratch (device globals: no allocation allowed in kernel_launch)
__device__ float g_KcatT[QTOT * NX];   // [q][i], q=(t*NU+j) holds (A^{L-1-t}B)^T
__device__ float g_AL[NX * NX];        // A^L row-major
__device__ float g_buf[(size_t)C_CHUNKS * NX * R];  // Pfin, overwritten by Xstart

// ---------------- packed f32x2 helpers ----------------
__device__ __forceinline__ ull pack2(float lo, float hi) {
    ull v; asm("mov.b64 %0,{%1,%2};" : "=l"(v) : "f"(lo), "f"(hi)); return v;
}
__device__ __forceinline__ void unpack2(ull v, float& lo, float& hi) {
    asm("mov.b64 {%0,%1},%2;" : "=f"(lo), "=f"(hi) : "l"(v));
}
// IN-PLACE packed fma: no output-register copy
__device__ __forceinline__ void fma2ip(ull& d, ull a, ull b) {
    asm("fma.rn.f32x2 %0,%1,%2,%0;" : "+l"(d) : "l"(a), "l"(b));
}

// ---------------------------------------------------------------------------
// Kernel 0 (v2): K[s]=A^s B (s=0..15) by doubling + A^16, all in smem,
// register-packed accumulators, ONE barrier per round. 512 threads.
// Thread t: output row i = t>>3; column-group = (t&7).
// ---------------------------------------------------------------------------
extern __shared__ float psm[];
__global__ void k_precompute(const float* __restrict__ A, const float* __restrict__ B) {
    float* sP = psm;            // 4096 floats
    float* sQ = psm + 4096;     // 4096
    float* sW = psm + 8192;     // [i][col], row stride 128
    const int t = threadIdx.x;  // 512
    const int i = t >> 3;       // 0..63
    const int g = t & 7;        // 0..7

    for (int idx = t; idx < NX * NX; idx += 512) sP[idx] = A[idx];
    for (int idx = t; idx < NX * NU; idx += 512) {
        int ii = idx / NU, j = idx % NU;
        sW[ii * QTOT + j] = B[idx];
    }
    __syncthreads();

    float* p = sP;
    float* q = sQ;
    int w = NU;  // 8 -> 16 -> 32 -> 64 -> 128
    for (int m = 0; m < 4; m++) {
        // ---- append: sW[:, w..2w) = p @ sW[:, 0..w) ----
        const int cw = w >> 3;          // cols per thread: 1,2,4,8
        if (cw == 1) {
            float s0 = 0.f, s1 = 0.f, s2 = 0.f, s3 = 0.f;
            #pragma unroll 4
            for (int k = 0; k < NX; k += 4) {
                s0 += p[i * NX + k + 0] * sW[(k + 0) * QTOT + g];
                s1 += p[i * NX + k + 1] * sW[(k + 1) * QTOT + g];
                s2 += p[i * NX + k + 2] * sW[(k + 2) * QTOT + g];
                s3 += p[i * NX + k + 3] * sW[(k + 3) * QTOT + g];
            }
            sW[i * QTOT + w + g] = (s0 + s1) + (s2 + s3);
        } else {
            const int jc0 = g * cw;
            const int nv = cw >> 1;     // 1,2,4 packed accs
            ull acc[4] = {0ull, 0ull, 0ull, 0ull};
            for (int k = 0; k < NX; k++) {
                float a = p[i * NX + k];
                ull pk = pack2(a, a);
                const ull* wr = (const ull*)(sW + k * QTOT + jc0);
                #pragma unroll
                for (int v = 0; v < 4; v++)
                    if (v < nv) fma2ip(acc[v], pk, wr[v]);
            }
            ull* out = (ull*)(sW + i * QTOT + w + jc0);
            #pragma unroll
            for (int v = 0; v < 4; v++)
                if (v < nv) out[v] = acc[v];
        }

        // ---- square: q = p @ p (reads only p; disjoint from append writes) ----
        {
            const int jb = g * 8;       // 8 output cols = 4 packed pairs
            ull acc[4] = {0ull, 0ull, 0ull, 0ull};
            for (int k = 0; k < NX; k++) {
                float a = p[i * NX + k];
                ull pk = pack2(a, a);
                const ulonglong2* pr = (const ulonglong2*)(p + k * NX + jb);
                ulonglong2 w0 = pr[0], w1 = pr[1];
                fma2ip(acc[0], pk, w0.x);
                fma2ip(acc[1], pk, w0.y);
                fma2ip(acc[2], pk, w1.x);
                fma2ip(acc[3], pk, w1.y);
            }
            ull* out = (ull*)(q + i * NX + jb);
            out[0] = acc[0]; out[1] = acc[1]; out[2] = acc[2]; out[3] = acc[3];
        }
        __syncthreads();   // one barrier per round
        float* tmp = p; p = q; q = tmp;
        w <<= 1;
    }

    // p = A^16
    for (int idx = t; idx < NX * NX; idx += 512) g_AL[idx] = p[idx];
    // scatter time-flipped transpose: KcatT[((L-1-s)*NU+j)*NX + i] = W[i][s*NU+j]
    for (int idx = t; idx < NX * QTOT; idx += 512) {
        int ii = idx >> 7, col = idx & 127;
        int s = col >> 3, j = col & 7;
        g_KcatT[(((L - 1 - s) * NU + j) * NX) + ii] = sW[ii * QTOT + col];
    }
}

// ---------------------------------------------------------------------------
// Kernel 1: Pfin[c] = Kcat(64x128) @ Uc(128x256) -> g_buf. Grid (256,4), 256 thr.
// ---------------------------------------------------------------------------
__global__ void k_phase1(const float* __restrict__ u) {
    __shared__ __align__(16) float sU[64 * 64];
    __shared__ __align__(16) float sKT[64 * 64];
    const int c = blockIdx.x;
    const int r0 = blockIdx.y * 64;
    const int t = threadIdx.x;
    const int r = t & 63;
    const int ig = t >> 6;

    ull acc2[8];
    #pragma unroll
    for (int m = 0; m < 8; m++) acc2[m] = 0ull;

    const float* Uc = u + (size_t)c * L * NU * R;

    for (int qb = 0; qb < QTOT / 64; qb++) {
        __syncthreads();
        #pragma unroll
        for (int m = 0; m < 16; m++) {
            int qq = m * 4 + ig;
            sU[qq * 64 + r] = Uc[(size_t)(qb * 64 + qq) * R + r0 + r];
        }
        for (int idx = t; idx < 4096; idx += 256)
            sKT[idx] = g_KcatT[qb * 64 * 64 + idx];
        __syncthreads();

        #pragma unroll 8
        for (int qq = 0; qq < 64; qq++) {
            float uval = sU[qq * 64 + r];
            ull uv = pack2(uval, uval);
            const ulonglong2* k2p = (const ulonglong2*)(sKT + qq * 64 + ig * 16);
            #pragma unroll
            for (int m2 = 0; m2 < 4; m2++) {
                ulonglong2 kk = k2p[m2];
                fma2ip(acc2[2 * m2 + 0], kk.x, uv);
                fma2ip(acc2[2 * m2 + 1], kk.y, uv);
            }
        }
    }
    #pragma unroll
    for (int m = 0; m < 8; m++) {
        float lo, hi; unpack2(acc2[m], lo, hi);
        int i = ig * 16 + 2 * m;
        g_buf[((size_t)c * NX + i) * R + r0 + r]     = lo;
        g_buf[((size_t)c * NX + i + 1) * R + r0 + r] = hi;
    }
}

// ---------------------------------------------------------------------------
// Kernel 2 (v2): boundary scan with 4-deep gmem prefetch pipeline.
// A^16-row cached in packed regs; x via LDS.64. 128 CTAs x 128 threads.
// ---------------------------------------------------------------------------
__global__ void k_phase2(const float* __restrict__ x0) {
    __shared__ __align__(16) float sxf[2][2][NX];  // [buf][r][i]
    const int t = threadIdx.x;  // 128
    const int r = t & 1;
    const int i = t >> 1;
    const int rg = blockIdx.x * 2 + r;

    ull a2[32];
    const ull* arow = (const ull*)(g_AL + i * NX);
    #pragma unroll
    for (int j2 = 0; j2 < 32; j2++) a2[j2] = arow[j2];

    float xi = x0[i * R + rg];
    sxf[0][r][i] = xi;
    __syncthreads();

    // 4-deep prefetch queue for Pfin loads (covers ~4 iterations of latency)
    float pfq[4];
    #pragma unroll
    for (int d = 0; d < 4; d++)
        pfq[d] = g_buf[((size_t)d * NX + i) * R + rg];

    int p = 0;
    for (int c = 0; c < C_CHUNKS; c++) {
        float pf = pfq[c & 3];
        float pf_future = (c + 4 < C_CHUNKS)
            ? g_buf[((size_t)(c + 4) * NX + i) * R + rg] : 0.f;
        g_buf[((size_t)c * NX + i) * R + rg] = xi;   // Xstart[c] (slot c read long ago)

        const ull* xsrc = (const ull*)&sxf[p][r][0];
        ull A0 = 0ull, A1 = 0ull, A2 = 0ull, A3 = 0ull;
        #pragma unroll
        for (int j2 = 0; j2 < 32; j2 += 4) {
            fma2ip(A0, a2[j2 + 0], xsrc[j2 + 0]);
            fma2ip(A1, a2[j2 + 1], xsrc[j2 + 1]);
            fma2ip(A2, a2[j2 + 2], xsrc[j2 + 2]);
            fma2ip(A3, a2[j2 + 3], xsrc[j2 + 3]);
        }
        float s0, s1, s2, s3, s4, s5, s6, s7;
        unpack2(A0, s0, s1); unpack2(A1, s2, s3);
        unpack2(A2, s4, s5); unpack2(A3, s6, s7);
        xi = (((s0 + s1) + (s2 + s3)) + ((s4 + s5) + (s6 + s7))) + pf;

        pfq[c & 3] = pf_future;
        sxf[p ^ 1][r][i] = xi;
        __syncthreads();
        p ^= 1;
    }
}

// ---------------------------------------------------------------------------
// Kernel 3: TWO columns per thread, packed f32x2 in-place, x_k in smem scratch.
// (identical to R7 best: 317us) 64 threads (2 warps), grid (C_CHUNKS, 2).
// ---------------------------------------------------------------------------
extern __shared__ __align__(16) char dsmem[];

__global__ void __launch_bounds__(64) k_phase3(
    const float* __restrict__ u, const float* __restrict__ A,
    const float* __restrict__ B, const float* __restrict__ Cy,
    const float* __restrict__ D,
    float* __restrict__ outY, float* __restrict__ outX)
{
    ull*   xs  = (ull*)dsmem;                          // [32][128] packed x pairs
    ull*   sA2 = (ull*)(dsmem + 32768);                // [j][i2] 64x32
    ull*   sB2 = (ull*)(dsmem + 32768 + 16384);        // [j][i2] 8x32
    ull*   sC2 = (ull*)(dsmem + 32768 + 16384 + 2048); // [o][j2] 8x32
    float* sD  = (float*)(dsmem + 32768 + 16384 + 4096);

    const int tid = threadIdx.x;                       // 64
    const int c = blockIdx.x;
    const int rA = blockIdx.y * 128 + tid;             // column a (col b = rA+64)

    for (int idx = tid; idx < 64 * 32; idx += 64) {
        int j = idx >> 5, i2 = idx & 31;
        sA2[idx] = pack2(A[(2 * i2) * NX + j], A[(2 * i2 + 1) * NX + j]);
    }
    for (int idx = tid; idx < NU * 32; idx += 64) {
        int j = idx >> 5, i2 = idx & 31;
        sB2[idx] = pack2(B[(2 * i2) * NU + j], B[(2 * i2 + 1) * NU + j]);
    }
    for (int idx = tid; idx < NY * 32; idx += 64) {
        int o = idx >> 5, j2 = idx & 31;
        sC2[idx] = pack2(Cy[o * NX + 2 * j2], Cy[o * NX + 2 * j2 + 1]);
    }
    if (tid < NY * NU) sD[tid] = D[tid];

    ull acc2a[32], acc2b[32];
    {
        const float* xsa = g_buf + (size_t)c * NX * R + rA;
        #pragma unroll
        for (int k = 0; k < 32; k++) {
            acc2a[k] = pack2(xsa[(2 * k) * R], xsa[(2 * k + 1) * R]);
            acc2b[k] = pack2(xsa[(2 * k) * R + 64], xsa[(2 * k + 1) * R + 64]);
        }
    }
    __syncthreads();

    const float* upa = u    + (size_t)c * L * NU * R + rA;
    float*       ypa = outY + (size_t)c * L * NY * R + rA;
    float*       xpa = outX + (size_t)c * L * NX * R + rA;

    #pragma unroll 1
    for (int step = 0; step < L; step++) {
        float ua[NU], ub[NU];
        #pragma unroll
        for (int j = 0; j < NU; j++) {
            ua[j] = upa[j * R];
            ub[j] = upa[j * R + 64];
        }

        #pragma unroll 2
        for (int o = 0; o < NY; o++) {
            ull ya = 0ull, yb = 0ull;
            const ulonglong2* c2 = (const ulonglong2*)(sC2 + o * 32);
            #pragma unroll
            for (int k2 = 0; k2 < 16; k2++) {
                ulonglong2 cc = c2[k2];
                fma2ip(ya, cc.x, acc2a[2 * k2 + 0]);
                fma2ip(ya, cc.y, acc2a[2 * k2 + 1]);
                fma2ip(yb, cc.x, acc2b[2 * k2 + 0]);
                fma2ip(yb, cc.y, acc2b[2 * k2 + 1]);
            }
            float la, ha; unpack2(ya, la, ha);
            float lb, hb; unpack2(yb, lb, hb);
            float dsa = 0.f, dsb = 0.f;
            #pragma unroll
            for (int j = 0; j < NU; j++) {
                float dv = sD[o * NU + j];
                dsa += dv * ua[j];
                dsb += dv * ub[j];
            }
            ypa[o * R]      = (la + ha) + dsa;
            ypa[o * R + 64] = (lb + hb) + dsb;
        }

        #pragma unroll
        for (int k = 0; k < 32; k++) {
            float la, ha; unpack2(acc2a[k], la, ha);
            float lb, hb; unpack2(acc2b[k], lb, hb);
            xpa[(2 * k) * R]          = la;
            xpa[(2 * k + 1) * R]      = ha;
            xpa[(2 * k) * R + 64]     = lb;
            xpa[(2 * k + 1) * R + 64] = hb;
            xs[k * 128 + tid]      = acc2a[k];
            xs[k * 128 + 64 + tid] = acc2b[k];
        }

        {
            #pragma unroll
            for (int k = 0; k < 32; k++) { acc2a[k] = 0ull; acc2b[k] = 0ull; }
            #pragma unroll 2
            for (int j = 0; j < NU; j++) {
                ull uaj = pack2(ua[j], ua[j]);
                ull ubj = pack2(ub[j], ub[j]);
                const ulonglong2* bj = (const ulonglong2*)(sB2 + j * 32);
                #pragma unroll
                for (int k2 = 0; k2 < 16; k2++) {
                    ulonglong2 bb = bj[k2];
                    fma2ip(acc2a[2 * k2 + 0], bb.x, uaj);
                    fma2ip(acc2a[2 * k2 + 1], bb.y, uaj);
                    fma2ip(acc2b[2 * k2 + 0], bb.x, ubj);
                    fma2ip(acc2b[2 * k2 + 1], bb.y, ubj);
                }
            }
        }

        #pragma unroll 2
        for (int j2 = 0; j2 < 32; j2++) {
            ull pa = xs[j2 * 128 + tid];
            ull pb = xs[j2 * 128 + 64 + tid];
            float xa0, xa1; unpack2(pa, xa0, xa1);
            float xb0, xb1; unpack2(pb, xb0, xb1);
            ull sa0 = pack2(xa0, xa0), sa1 = pack2(xa1, xa1);
            ull sb0 = pack2(xb0, xb0), sb1 = pack2(xb1, xb1);
            const ulonglong2* A0 = (const ulonglong2*)(sA2 + (2 * j2) * 32);
            const ulonglong2* A1 = (const ulonglong2*)(sA2 + (2 * j2 + 1) * 32);
            #pragma unroll
            for (int k2 = 0; k2 < 16; k2++) {
                ulonglong2 aa = A0[k2];
                fma2ip(acc2a[2 * k2 + 0], aa.x, sa0);
                fma2ip(acc2a[2 * k2 + 1], aa.y, sa0);
                fma2ip(acc2b[2 * k2 + 0], aa.x, sb0);
                fma2ip(acc2b[2 * k2 + 1], aa.y, sb0);
                ulonglong2 ab = A1[k2];
                fma2ip(acc2a[2 * k2 + 0], ab.x, sa1);
                fma2ip(acc2a[2 * k2 + 1], ab.y, sa1);
                fma2ip(acc2b[2 * k2 + 0], ab.x, sb1);
                fma2ip(acc2b[2 * k2 + 1], ab.y, sb1);
            }
        }

        upa += NU * R;
        ypa += NY * R;
        xpa += NX * R;
    }
}

#define SMEM_P3 (32768 + 16384 + 2048 + 2048 + 256)
#define SMEM_P0 ((4096 + 4096 + 8192) * 4)

// ---------------------------------------------------------------------------
extern "C" void kernel_launch(void* const* d_in, const int* in_sizes, int n_in,
                              void* d_out, int out_size) {
    const float* u  = (const float*)d_in[0];
    const float* x0 = (const float*)d_in[1];
    const float* A  = (const float*)d_in[2];
    const float* B  = (const float*)d_in[3];
    const float* Cy = (const float*)d_in[4];
    const float* D  = (const float*)d_in[5];
    float* outY = (float*)d_out;
    float* outX = (float*)d_out + (size_t)N_STEPS * NY * R;

    cudaFuncSetAttribute(k_phase3, cudaFuncAttributeMaxDynamicSharedMemorySize, SMEM_P3);
    cudaFuncSetAttribute(k_precompute, cudaFuncAttributeMaxDynamicSharedMemorySize, SMEM_P0);

    k_precompute<<<1, 512, SMEM_P0>>>(A, B);
    k_phase1<<<dim3(C_CHUNKS, R / 64), 256>>>(u);
    k_phase2<<<R / 2, 128>>>(x0);
    k_phase3<<<dim3(C_CHUNKS, 2), 64, SMEM_P3>>>(u, A, B, Cy, D, outY, outX);
}